// round 1
// baseline (speedup 1.0000x reference)
#include <cuda_runtime.h>
#include <math.h>

#define NN 12800
#define GG 128
#define EB 51200
#define EC 204800

// ---------------- scratch (no allocations allowed) ----------------
__device__ float g_hA[NN*128];
__device__ float g_hB[NN*128];
__device__ float g_ef[EB*128];
__device__ float g_X[NN*512];      // [A1 | A2+b1 | B1 | B2+preb] per node
__device__ float g_C[EB*128];      // ef @ P3 per layer
__device__ float g_agg[NN*1024];   // [bond agg(512) | comp agg(512)]
__device__ float g_t1[NN*128];
__device__ float g_Wx[5*128*512];
__device__ float g_bx[5*512];
__device__ float g_We[5*1152*128];

// ---------------- weight packing ----------------
__global__ void pack_wx_kernel(const float* __restrict__ pcW1, const float* __restrict__ preW,
                               const float* __restrict__ pcB1, const float* __restrict__ preB) {
    int idx = blockIdx.x * 256 + threadIdx.x;
    if (idx < 5*128*512) {
        int l = idx >> 16;
        int rem = idx & 65535;
        int k = rem >> 9;
        int c = rem & 511;
        float v;
        if (c < 128)      v = pcW1[l*32768 + k*128 + c];
        else if (c < 256) v = pcW1[l*32768 + (128+k)*128 + (c-128)];
        else if (c < 384) v = preW[l*49152 + k*128 + (c-256)];
        else              v = preW[l*49152 + (128+k)*128 + (c-384)];
        g_Wx[idx] = v;
    }
    if (idx < 5*512) {
        int l = idx >> 9, c = idx & 511;
        float v = 0.f;
        if (c >= 128 && c < 256) v = pcB1[l*128 + (c-128)];
        else if (c >= 384)       v = preB[l*128 + (c-384)];
        g_bx[idx] = v;
    }
}

__global__ void pack_we_kernel(const float* __restrict__ postW) {
    int idx = blockIdx.x * 256 + threadIdx.x;
    if (idx >= 5*1152*128) return;
    int l = idx / 147456;
    int rem = idx - l*147456;
    int r = rem >> 7, j = rem & 127;
    const float* Wl = postW + (size_t)l*409600;
    float log5  = logf(5.f);
    float log17 = logf(17.f);
    float v;
    if (r < 128) {
        v = Wl[r*128 + j] + ((r == j) ? 1.f : 0.f);   // residual folded in
    } else if (r < 640) {
        int rp = r - 128;
        v = Wl[(128+rp)*128+j] + log5*Wl[(640+rp)*128+j] + Wl[(1152+rp)*128+j]*(1.f/log5);
    } else {
        int rp = r - 640;
        v = Wl[(1664+rp)*128+j] + log17*Wl[(2176+rp)*128+j] + Wl[(2688+rp)*128+j]*(1.f/log17);
    }
    g_We[idx] = v;
}

// ---------------- generic tiled GEMM: out = act(A @ W + bias) ----------------
// A virtually concatenated: cols [0,Ksplit) from A0, [Ksplit,K) from A1.
template<bool RELU>
__global__ __launch_bounds__(256) void gemm_kernel(
    const float* __restrict__ A0, int lda0,
    const float* __restrict__ A1, int lda1, int Ksplit,
    const float* __restrict__ W, int ldw,
    const float* __restrict__ bias,
    float* __restrict__ out, int ldo, int K)
{
    __shared__ float As[16][64];   // k-major
    __shared__ float Bs[16][128];
    const int t  = threadIdx.x;
    const int m0 = blockIdx.x * 64;
    const int n0 = blockIdx.y * 128;
    const int tc = t & 31, tr = t >> 5;
    const int ar = t >> 2;            // 0..63
    const int akq = (t & 3) << 2;     // 0,4,8,12

    float acc[8][4];
#pragma unroll
    for (int i = 0; i < 8; i++)
#pragma unroll
        for (int c = 0; c < 4; c++) acc[i][c] = 0.f;

    for (int k0 = 0; k0 < K; k0 += 16) {
        int kg = k0 + akq;
        const float* ap = (kg < Ksplit)
            ? (A0 + (size_t)(m0 + ar) * lda0 + kg)
            : (A1 + (size_t)(m0 + ar) * lda1 + (kg - Ksplit));
        float4 av = *(const float4*)ap;
        As[akq+0][ar] = av.x; As[akq+1][ar] = av.y;
        As[akq+2][ar] = av.z; As[akq+3][ar] = av.w;
#pragma unroll
        for (int i = 0; i < 2; i++) {
            int off = t*8 + i*4;
            int kk = off >> 7, j = off & 127;
            *(float4*)&Bs[kk][j] = *(const float4*)&W[(size_t)(k0+kk)*ldw + n0 + j];
        }
        __syncthreads();
#pragma unroll
        for (int kk = 0; kk < 16; kk++) {
            float a[8];
            *(float4*)&a[0] = *(const float4*)&As[kk][tr*8];
            *(float4*)&a[4] = *(const float4*)&As[kk][tr*8+4];
            float4 b = *(const float4*)&Bs[kk][tc*4];
#pragma unroll
            for (int i = 0; i < 8; i++) {
                acc[i][0] += a[i]*b.x; acc[i][1] += a[i]*b.y;
                acc[i][2] += a[i]*b.z; acc[i][3] += a[i]*b.w;
            }
        }
        __syncthreads();
    }
    float bv[4] = {0.f, 0.f, 0.f, 0.f};
    if (bias) {
        float4 b4 = *(const float4*)&bias[n0 + tc*4];
        bv[0]=b4.x; bv[1]=b4.y; bv[2]=b4.z; bv[3]=b4.w;
    }
#pragma unroll
    for (int i = 0; i < 8; i++) {
        float4 o;
        float* po = (float*)&o;
#pragma unroll
        for (int c = 0; c < 4; c++) {
            float v = acc[i][c] + bv[c];
            po[c] = RELU ? fmaxf(v, 0.f) : v;
        }
        *(float4*)&out[(size_t)(m0 + tr*8 + i)*ldo + n0 + tc*4] = o;
    }
}

// ---------------- fused comp-edge kernel ----------------
// Per 64-edge tile: a = relu(X[src,0:128] + X[dst,128:256]); m = a @ W2 + b2;
// gate = sigmoid(m . seW + seb); ec = m*gate; PNA stats over 16-edge groups.
__global__ __launch_bounds__(256) void comp_kernel(
    const int* __restrict__ src,
    const float* __restrict__ W2,
    const float* __restrict__ b2,
    const float* __restrict__ seW,
    const float* __restrict__ seB)
{
    __shared__ float As[128][64];    // k-major, 32 KB
    __shared__ float Bs[16][128];    // 8 KB
    __shared__ float sRed[8][16];
    const int t  = threadIdx.x;
    const int e0 = blockIdx.x * 64;

    {   // build A tile: gather + add + relu
        int e = t & 63, kq = t >> 6;
        int s = src[e0 + e];
        int node = (e0 >> 4) + (e >> 4);
        const float* x1 = g_X + (size_t)s*512;
        const float* x2 = g_X + (size_t)node*512 + 128;
#pragma unroll
        for (int q = 0; q < 8; q++) {
            int k = kq*32 + q*4;
            float4 a = *(const float4*)(x1 + k);
            float4 b = *(const float4*)(x2 + k);
            As[k+0][e] = fmaxf(a.x+b.x, 0.f);
            As[k+1][e] = fmaxf(a.y+b.y, 0.f);
            As[k+2][e] = fmaxf(a.z+b.z, 0.f);
            As[k+3][e] = fmaxf(a.w+b.w, 0.f);
        }
    }
    __syncthreads();

    const int tc = t & 63, tr = t >> 6;  // tc: col pair, tr: node group (16 rows)
    float acc[16][2];
#pragma unroll
    for (int i = 0; i < 16; i++) { acc[i][0] = 0.f; acc[i][1] = 0.f; }

    for (int k0 = 0; k0 < 128; k0 += 16) {
#pragma unroll
        for (int i = 0; i < 2; i++) {
            int off = t*8 + i*4;
            int kk = off >> 7, j = off & 127;
            *(float4*)&Bs[kk][j] = *(const float4*)&W2[(k0+kk)*128 + j];
        }
        __syncthreads();
#pragma unroll
        for (int kk = 0; kk < 16; kk++) {
            int k = k0 + kk;
            float a[16];
            *(float4*)&a[0]  = *(const float4*)&As[k][tr*16+0];
            *(float4*)&a[4]  = *(const float4*)&As[k][tr*16+4];
            *(float4*)&a[8]  = *(const float4*)&As[k][tr*16+8];
            *(float4*)&a[12] = *(const float4*)&As[k][tr*16+12];
            float2 b = *(const float2*)&Bs[kk][tc*2];
#pragma unroll
            for (int i = 0; i < 16; i++) {
                acc[i][0] += a[i]*b.x;
                acc[i][1] += a[i]*b.y;
            }
        }
        __syncthreads();
    }

    // epilogue: bias, gate (row reduction), PNA stats over 16 rows
    int j0 = tc*2;
    float bb0 = b2[j0], bb1 = b2[j0+1];
    float sw0 = seW[j0], sw1 = seW[j0+1];
    float p[16];
#pragma unroll
    for (int i = 0; i < 16; i++) {
        acc[i][0] += bb0; acc[i][1] += bb1;
        p[i] = acc[i][0]*sw0 + acc[i][1]*sw1;
    }
#pragma unroll
    for (int off = 16; off > 0; off >>= 1)
#pragma unroll
        for (int i = 0; i < 16; i++)
            p[i] += __shfl_xor_sync(0xffffffffu, p[i], off);
    if ((t & 31) == 0) {
        int w = t >> 5;
#pragma unroll
        for (int i = 0; i < 16; i++) sRed[w][i] = p[i];
    }
    __syncthreads();
    float sb = seB[0];
    float s0=0.f,s1=0.f,q0=0.f,q1=0.f;
    float mx0=-INFINITY,mx1=-INFINITY,mn0=INFINITY,mn1=INFINITY;
#pragma unroll
    for (int i = 0; i < 16; i++) {
        float sum = sRed[2*tr][i] + sRed[2*tr+1][i] + sb;
        float g = 1.f / (1.f + expf(-sum));
        float e0v = acc[i][0]*g, e1v = acc[i][1]*g;
        s0 += e0v; q0 += e0v*e0v; mx0 = fmaxf(mx0, e0v); mn0 = fminf(mn0, e0v);
        s1 += e1v; q1 += e1v*e1v; mx1 = fmaxf(mx1, e1v); mn1 = fminf(mn1, e1v);
    }
    int node = (e0 >> 4) + tr;
    float* o = g_agg + (size_t)node*1024 + 512 + j0;
    float m0v = s0*0.0625f, m1v = s1*0.0625f;
    float sd0 = sqrtf(fmaxf(q0*0.0625f - m0v*m0v, 0.f) + 1e-5f);
    float sd1 = sqrtf(fmaxf(q1*0.0625f - m1v*m1v, 0.f) + 1e-5f);
    o[0]   = m0v; o[1]   = m1v;
    o[128] = mx0; o[129] = mx1;
    o[256] = mn0; o[257] = mn1;
    o[384] = sd0; o[385] = sd1;
}

// ---------------- bond-edge PNA (gather-add only, no GEMM) ----------------
__global__ __launch_bounds__(256) void bond_kernel(const int* __restrict__ src) {
    int idx = blockIdx.x*256 + threadIdx.x;   // NN*128 total
    int n = idx >> 7, j = idx & 127;
    float base = g_X[(size_t)n*512 + 384 + j];
    float s=0.f, q=0.f, mx=-INFINITY, mn=INFINITY;
#pragma unroll
    for (int e = 0; e < 4; e++) {
        int ei = n*4 + e;
        int sv = src[ei];
        float v = g_X[(size_t)sv*512 + 256 + j] + base + g_C[(size_t)ei*128 + j];
        s += v; q += v*v; mx = fmaxf(mx, v); mn = fminf(mn, v);
    }
    float mean = s*0.25f;
    float sd = sqrtf(fmaxf(q*0.25f - mean*mean, 0.f) + 1e-5f);
    float* o = g_agg + (size_t)n*1024 + j;
    o[0] = mean; o[128] = mx; o[256] = mn; o[384] = sd;
}

// ---------------- readout: per-graph sum/mean/max + 2-layer MLP ----------------
__global__ __launch_bounds__(128) void readout_kernel(
    const float* __restrict__ h3,
    const float* __restrict__ W1, const float* __restrict__ b1,
    const float* __restrict__ W2, const float* __restrict__ b2,
    float* __restrict__ out)
{
    __shared__ float r[384];
    __shared__ float tb[128];
    int g = blockIdx.x, j = threadIdx.x;
    const float* p = h3 + (size_t)g*100*128 + j;
    float s = 0.f, mx = -INFINITY;
    for (int i = 0; i < 100; i++) {
        float v = p[i*128];
        s += v; mx = fmaxf(mx, v);
    }
    r[j] = s; r[128+j] = s/100.f; r[256+j] = mx;
    __syncthreads();
    float a = b1[j];
    for (int k = 0; k < 384; k++) a += r[k]*W1[k*128 + j];
    tb[j] = fmaxf(a, 0.f);
    __syncthreads();
    if (j < 32) {
        float o = b2[j];
        for (int k = 0; k < 128; k++) o += tb[k]*W2[k*32 + j];
        out[g*32 + j] = o;
    }
}

// ---------------- launcher ----------------
extern "C" void kernel_launch(void* const* d_in, const int* in_sizes, int n_in,
                              void* d_out, int out_size) {
    const float* node_feat = (const float*)d_in[0];
    const float* edge_feat = (const float*)d_in[1];
    const int*   bond_src  = (const int*)d_in[2];
    const int*   comp_src  = (const int*)d_in[4];
    const float* in_W   = (const float*)d_in[7];
    const float* in_b   = (const float*)d_in[8];
    const float* ein_W  = (const float*)d_in[9];
    const float* ein_b  = (const float*)d_in[10];
    const float* pre_W  = (const float*)d_in[11];
    const float* pre_b  = (const float*)d_in[12];
    const float* pc_W1  = (const float*)d_in[13];
    const float* pc_b1  = (const float*)d_in[14];
    const float* pc_W2  = (const float*)d_in[15];
    const float* pc_b2  = (const float*)d_in[16];
    const float* se_W   = (const float*)d_in[17];
    const float* se_b   = (const float*)d_in[18];
    const float* post_W = (const float*)d_in[19];
    const float* post_b = (const float*)d_in[20];
    const float* outn_W1 = (const float*)d_in[21];
    const float* outn_b1 = (const float*)d_in[22];
    const float* outn_W2 = (const float*)d_in[23];
    const float* outn_b2 = (const float*)d_in[24];
    const float* ro_W1 = (const float*)d_in[25];
    const float* ro_b1 = (const float*)d_in[26];
    const float* ro_W2 = (const float*)d_in[27];
    const float* ro_b2 = (const float*)d_in[28];

    float *hA, *hB, *ef, *X, *C, *agg, *t1, *Wx, *bx, *We;
    cudaGetSymbolAddress((void**)&hA, g_hA);
    cudaGetSymbolAddress((void**)&hB, g_hB);
    cudaGetSymbolAddress((void**)&ef, g_ef);
    cudaGetSymbolAddress((void**)&X,  g_X);
    cudaGetSymbolAddress((void**)&C,  g_C);
    cudaGetSymbolAddress((void**)&agg, g_agg);
    cudaGetSymbolAddress((void**)&t1, g_t1);
    cudaGetSymbolAddress((void**)&Wx, g_Wx);
    cudaGetSymbolAddress((void**)&bx, g_bx);
    cudaGetSymbolAddress((void**)&We, g_We);

    pack_wx_kernel<<<(5*128*512 + 255)/256, 256>>>(pc_W1, pre_W, pc_b1, pre_b);
    pack_we_kernel<<<(5*1152*128 + 255)/256, 256>>>(post_W);

    // input transforms
    gemm_kernel<true><<<dim3(NN/64, 1), 256>>>(node_feat, 64, node_feat, 64, 64,
                                               in_W, 128, in_b, hA, 128, 64);
    gemm_kernel<true><<<dim3(EB/64, 1), 256>>>(edge_feat, 16, edge_feat, 16, 16,
                                               ein_W, 128, ein_b, ef, 128, 16);

    float* cur = hA;
    float* nxt = hB;
    for (int l = 0; l < 5; l++) {
        // X = h @ [W1a | W1b | P1 | P2] + [0 | b1 | 0 | preb]
        gemm_kernel<false><<<dim3(NN/64, 4), 256>>>(cur, 128, cur, 128, 128,
                                                    Wx + l*65536, 512, bx + l*512, X, 512, 128);
        // C = ef @ P3
        gemm_kernel<false><<<dim3(EB/64, 1), 256>>>(ef, 128, ef, 128, 128,
                                                    pre_W + (size_t)l*49152 + 256*128, 128,
                                                    nullptr, C, 128, 128);
        bond_kernel<<<NN*128/256, 256>>>(bond_src);
        comp_kernel<<<EC/64, 256>>>(comp_src, pc_W2 + (size_t)l*16384, pc_b2 + l*128,
                                    se_W + l*128, se_b + l);
        // h_next = [h | agg] @ W_eff + post_b   (residual + scalers folded into W_eff)
        gemm_kernel<false><<<dim3(NN/64, 1), 256>>>(cur, 128, agg, 1024, 128,
                                                    We + l*147456, 128, post_b + l*128,
                                                    nxt, 128, 1152);
        float* tmp = cur; cur = nxt; nxt = tmp;
    }

    // node-wise output MLP
    gemm_kernel<true ><<<dim3(NN/64, 1), 256>>>(cur, 128, cur, 128, 128,
                                                outn_W1, 128, outn_b1, t1, 128, 128);
    gemm_kernel<false><<<dim3(NN/64, 1), 256>>>(t1, 128, t1, 128, 128,
                                                outn_W2, 128, outn_b2, nxt, 128, 128);
    // readout
    readout_kernel<<<GG, 128>>>(nxt, ro_W1, ro_b1, ro_W2, ro_b2, (float*)d_out);
}